// round 9
// baseline (speedup 1.0000x reference)
#include <cuda_runtime.h>
#include <cuda_bf16.h>
#include <cstdint>

#define NN 100000
#define EE 1600000
#define HD 128
#define NBLK 391   // ceil(NN/256)
#define NSTAT 512  // bn partial blocks

// ---------------- scratch (device globals; no allocations) ----------------
__device__ int   g_is32;
__device__ int   g_degi[NN];
__device__ float g_dis[NN];
__device__ int   g_rowptr[NN + 1];
__device__ int   g_cursor[NN];
__device__ int   g_bsums[512];
__device__ int   g_csr_src[EE];
__device__ float g_csr_w[EE];
__device__ float g_h[(size_t)NN * HD];
__device__ float g_z[(size_t)NN * HD];
__device__ float g_part1[NSTAT * HD];
__device__ float g_part2[NSTAT * HD];
__device__ float g_scale[HD];
__device__ float g_shift[HD];

// ---------------- dtype detect + degree zero (merged) ----------------
__global__ void deg_zero_k(const void* ei) {
    int i = blockIdx.x * blockDim.x + threadIdx.x;
    if (i < NN) g_degi[i] = 0;
    if (i == 0) {
        const long long* p = (const long long*)ei;
        int is32 = 0;
#pragma unroll
        for (int t = 0; t < 16; t++) {
            long long v = p[t];
            if (v < 0 || v >= NN) is32 = 1;
        }
        g_is32 = is32;
    }
}

__device__ __forceinline__ int edge_at(const void* ei, size_t pos) {
    if (g_is32) return ((const int*)ei)[pos];
    return (int)((const long long*)ei)[pos];
}

// ---------------- CSR build ----------------
__global__ void count_deg_k(const void* __restrict__ ei) {
    int e = blockIdx.x * blockDim.x + threadIdx.x;
    if (e < EE) atomicAdd(&g_degi[edge_at(ei, (size_t)EE + e)], 1);
}

__global__ void __launch_bounds__(256) block_red_k() {
    __shared__ int sm[256];
    int tid = threadIdx.x;
    int i = blockIdx.x * 256 + tid;
    sm[tid] = (i < NN) ? g_degi[i] : 0;
    __syncthreads();
    for (int off = 128; off > 0; off >>= 1) {
        if (tid < off) sm[tid] += sm[tid + off];
        __syncthreads();
    }
    if (tid == 0) g_bsums[blockIdx.x] = sm[0];
}

__global__ void __launch_bounds__(512) scan_sums_k() {
    __shared__ int sm[512];
    int tid = threadIdx.x;
    int v = (tid < NBLK) ? g_bsums[tid] : 0;
    sm[tid] = v;
    __syncthreads();
    for (int off = 1; off < 512; off <<= 1) {
        int add = (tid >= off) ? sm[tid - off] : 0;
        __syncthreads();
        sm[tid] += add;
        __syncthreads();
    }
    if (tid < NBLK) g_bsums[tid] = sm[tid] - v;  // exclusive
}

__global__ void __launch_bounds__(256) rowptr_k() {
    __shared__ int sm[256];
    int tid = threadIdx.x;
    int i = blockIdx.x * 256 + tid;
    int v = (i < NN) ? g_degi[i] : 0;
    sm[tid] = v;
    __syncthreads();
    for (int off = 1; off < 256; off <<= 1) {
        int add = (tid >= off) ? sm[tid - off] : 0;
        __syncthreads();
        sm[tid] += add;
        __syncthreads();
    }
    if (i < NN) {
        int base = g_bsums[blockIdx.x];
        g_rowptr[i] = base + sm[tid] - v;
        if (i == NN - 1) g_rowptr[NN] = base + sm[tid];
        g_cursor[i] = 0;
        g_dis[i] = rsqrtf((float)v + 1.0f);  // +1 self loop
    }
}

__global__ void csr_fill_k(const void* __restrict__ ei) {
    int e = blockIdx.x * blockDim.x + threadIdx.x;
    if (e >= EE) return;
    int r = edge_at(ei, e);
    int c = edge_at(ei, (size_t)EE + e);
    int pos = g_rowptr[c] + atomicAdd(&g_cursor[c], 1);
    g_csr_src[pos] = r;
    g_csr_w[pos] = g_dis[r] * g_dis[c];
}

// ---------------- tf32 tensor-core GEMM: g_h = f(A) @ W ----------------
__device__ __forceinline__ uint32_t f2tf32(float f) {
    uint32_t u;
    asm("cvt.rna.tf32.f32 %0, %1;" : "=r"(u) : "f"(f));
    return u;
}

// Paired-fragment layout: element (r, sub, tig) is a uint2 holding
// (k = 8*sub+tig, k = 8*sub+tig+4). Row stride 20 uint2 (stride%16==4
// => conflict-free across lanes g*4+tig). As: 20KB, Wt: 20KB.
#define SP 20

__global__ void __launch_bounds__(256) gemm_tc_k(const float* __restrict__ Ain,
                                                 const float* __restrict__ W,
                                                 int use_bn) {
    __shared__ uint2 As[128 * SP];
    __shared__ uint2 Wt[128 * SP];
    uint32_t* AsU = (uint32_t*)As;
    uint32_t* WtU = (uint32_t*)Wt;
    const float* A = Ain ? Ain : g_z;
    int tid = threadIdx.x;
    int warp = tid >> 5, lane = tid & 31;
    int g = lane >> 2, tig = lane & 3;
    int row0 = blockIdx.x * 128;
    int wrow = warp * 16;

    float acc[16][4];
#pragma unroll
    for (int nt = 0; nt < 16; nt++)
#pragma unroll
        for (int i = 0; i < 4; i++) acc[nt][i] = 0.f;

    for (int kc = 0; kc < 4; kc++) {
        __syncthreads();
        // stage A chunk (BN+ReLU fused): rows [row0,+128) x k [32kc,+32)
        for (int i4 = tid; i4 < 128 * 8; i4 += 256) {
            int r = i4 >> 3, c4 = i4 & 7;
            int grow = row0 + r;
            float4 v = make_float4(0.f, 0.f, 0.f, 0.f);
            if (grow < NN)
                v = ((const float4*)(A + (size_t)grow * HD + kc * 32))[c4];
            if (use_bn) {
                float4 sc = ((const float4*)g_scale)[kc * 8 + c4];
                float4 sh = ((const float4*)g_shift)[kc * 8 + c4];
                v.x = fmaxf(fmaf(v.x, sc.x, sh.x), 0.f);
                v.y = fmaxf(fmaf(v.y, sc.y, sh.y), 0.f);
                v.z = fmaxf(fmaf(v.z, sc.z, sh.z), 0.f);
                v.w = fmaxf(fmaf(v.w, sc.w, sh.w), 0.f);
            }
            int sub = c4 >> 1, half = c4 & 1;
            int base = (r * SP + sub * 4) * 2 + half;
            AsU[base + 0] = f2tf32(v.x);
            AsU[base + 2] = f2tf32(v.y);
            AsU[base + 4] = f2tf32(v.z);
            AsU[base + 6] = f2tf32(v.w);
        }
        // stage W chunk transposed+paired: (k, n) -> Wt[n][sub][tig](half)
        for (int i = tid; i < 32 * 128; i += 256) {
            int kk = i >> 7, n = i & 127;
            int sub = kk >> 3, rem = kk & 7;
            int tg = rem & 3, half = rem >> 2;
            WtU[(n * SP + sub * 4 + tg) * 2 + half] =
                f2tf32(W[(size_t)(kc * 32 + kk) * HD + n]);
        }
        __syncthreads();

#pragma unroll
        for (int sub = 0; sub < 4; sub++) {
            uint2 a01 = As[(wrow + g) * SP + sub * 4 + tig];      // (a0,a2)
            uint2 a23 = As[(wrow + g + 8) * SP + sub * 4 + tig];  // (a1,a3)
#pragma unroll
            for (int nt = 0; nt < 16; nt++) {
                uint2 b = Wt[(nt * 8 + g) * SP + sub * 4 + tig];  // (b0,b1)
                asm volatile(
                    "mma.sync.aligned.m16n8k8.row.col.f32.tf32.tf32.f32 "
                    "{%0,%1,%2,%3}, {%4,%5,%6,%7}, {%8,%9}, {%0,%1,%2,%3};"
                    : "+f"(acc[nt][0]), "+f"(acc[nt][1]),
                      "+f"(acc[nt][2]), "+f"(acc[nt][3])
                    : "r"(a01.x), "r"(a23.x), "r"(a01.y), "r"(a23.y),
                      "r"(b.x), "r"(b.y));
            }
        }
    }

    int r0 = row0 + wrow + g;
    int r1 = r0 + 8;
#pragma unroll
    for (int nt = 0; nt < 16; nt++) {
        int col = nt * 8 + 2 * tig;
        if (r0 < NN)
            *(float2*)(g_h + (size_t)r0 * HD + col) = make_float2(acc[nt][0], acc[nt][1]);
        if (r1 < NN)
            *(float2*)(g_h + (size_t)r1 * HD + col) = make_float2(acc[nt][2], acc[nt][3]);
    }
}

// ---------------- aggregation (gather, 4-wide pipelined) ----------------
__global__ void __launch_bounds__(256) aggregate_k(const float* __restrict__ b,
                                                   float* __restrict__ outp) {
    int warp = threadIdx.x >> 5;
    int lane = threadIdx.x & 31;
    int n = blockIdx.x * 8 + warp;
    if (n >= NN) return;

    const float4* h4 = (const float4*)g_h;
    float d = g_dis[n];
    float s = d * d;
    float4 bv = ((const float4*)b)[lane];
    float4 acc0 = h4[(size_t)n * 32 + lane];
    acc0.x = fmaf(acc0.x, s, bv.x);
    acc0.y = fmaf(acc0.y, s, bv.y);
    acc0.z = fmaf(acc0.z, s, bv.z);
    acc0.w = fmaf(acc0.w, s, bv.w);
    float4 acc1 = make_float4(0.f, 0.f, 0.f, 0.f);
    float4 acc2 = make_float4(0.f, 0.f, 0.f, 0.f);
    float4 acc3 = make_float4(0.f, 0.f, 0.f, 0.f);

    int p0 = g_rowptr[n];
    int p1 = g_rowptr[n + 1];
    int p = p0;
    for (; p + 4 <= p1; p += 4) {
        int s0 = g_csr_src[p];
        int s1 = g_csr_src[p + 1];
        int s2 = g_csr_src[p + 2];
        int s3 = g_csr_src[p + 3];
        float w0 = g_csr_w[p];
        float w1 = g_csr_w[p + 1];
        float w2 = g_csr_w[p + 2];
        float w3 = g_csr_w[p + 3];
        float4 v0 = h4[(size_t)s0 * 32 + lane];
        float4 v1 = h4[(size_t)s1 * 32 + lane];
        float4 v2 = h4[(size_t)s2 * 32 + lane];
        float4 v3 = h4[(size_t)s3 * 32 + lane];
        acc0.x = fmaf(w0, v0.x, acc0.x); acc0.y = fmaf(w0, v0.y, acc0.y);
        acc0.z = fmaf(w0, v0.z, acc0.z); acc0.w = fmaf(w0, v0.w, acc0.w);
        acc1.x = fmaf(w1, v1.x, acc1.x); acc1.y = fmaf(w1, v1.y, acc1.y);
        acc1.z = fmaf(w1, v1.z, acc1.z); acc1.w = fmaf(w1, v1.w, acc1.w);
        acc2.x = fmaf(w2, v2.x, acc2.x); acc2.y = fmaf(w2, v2.y, acc2.y);
        acc2.z = fmaf(w2, v2.z, acc2.z); acc2.w = fmaf(w2, v2.w, acc2.w);
        acc3.x = fmaf(w3, v3.x, acc3.x); acc3.y = fmaf(w3, v3.y, acc3.y);
        acc3.z = fmaf(w3, v3.z, acc3.z); acc3.w = fmaf(w3, v3.w, acc3.w);
    }
    for (; p < p1; p++) {
        int src = g_csr_src[p];
        float wt = g_csr_w[p];
        float4 v = h4[(size_t)src * 32 + lane];
        acc0.x = fmaf(wt, v.x, acc0.x); acc0.y = fmaf(wt, v.y, acc0.y);
        acc0.z = fmaf(wt, v.z, acc0.z); acc0.w = fmaf(wt, v.w, acc0.w);
    }
    acc0.x += acc1.x + acc2.x + acc3.x;
    acc0.y += acc1.y + acc2.y + acc3.y;
    acc0.z += acc1.z + acc2.z + acc3.z;
    acc0.w += acc1.w + acc2.w + acc3.w;

    float* dst = outp ? outp : g_z;
    ((float4*)dst)[(size_t)n * 32 + lane] = acc0;
}

// ---------------- batchnorm stats (no atomics) ----------------
__global__ void __launch_bounds__(128) bn_stats_k() {
    int j = threadIdx.x;
    float sum = 0.f, sq = 0.f;
    for (int r = blockIdx.x; r < NN; r += NSTAT) {
        float v = g_z[(size_t)r * HD + j];
        sum += v;
        sq = fmaf(v, v, sq);
    }
    g_part1[blockIdx.x * HD + j] = sum;
    g_part2[blockIdx.x * HD + j] = sq;
}

__global__ void __launch_bounds__(128) bn_final_k(const float* __restrict__ g,
                                                  const float* __restrict__ be) {
    int j = threadIdx.x;
    float s1 = 0.f, s2 = 0.f;
#pragma unroll 8
    for (int i = 0; i < NSTAT; i++) {
        s1 += g_part1[i * HD + j];
        s2 += g_part2[i * HD + j];
    }
    float inv_n = 1.0f / (float)NN;
    float mu = s1 * inv_n;
    float var = s2 * inv_n - mu * mu;
    float sc = g[j] * rsqrtf(var + 1e-5f);
    g_scale[j] = sc;
    g_shift[j] = be[j] - mu * sc;
}

// ---------------- host: kernel launches ONLY ----------------
extern "C" void kernel_launch(void* const* d_in, const int* in_sizes, int n_in,
                              void* d_out, int out_size) {
    const float* x = (const float*)d_in[0];
    const void* ei = d_in[1];
    const float* W1 = (const float*)d_in[2];
    const float* b1 = (const float*)d_in[3];
    const float* W2 = (const float*)d_in[4];
    const float* b2 = (const float*)d_in[5];
    const float* W3 = (const float*)d_in[6];
    const float* b3 = (const float*)d_in[7];
    const float* g1 = (const float*)d_in[8];
    const float* be1 = (const float*)d_in[9];
    const float* g2 = (const float*)d_in[10];
    const float* be2 = (const float*)d_in[11];
    float* out = (float*)d_out;

    const int TB = 256;
    int nb_nodes = (NN + TB - 1) / TB;   // 391
    int nb_edges = (EE + TB - 1) / TB;   // 6250
    int nb_gemm = (NN + 127) / 128;      // 782
    int nb_agg = (NN + 7) / 8;           // 12500

    // ---- CSR build + norm precompute ----
    deg_zero_k<<<nb_nodes, TB>>>(ei);
    count_deg_k<<<nb_edges, TB>>>(ei);
    block_red_k<<<NBLK, 256>>>();
    scan_sums_k<<<1, 512>>>();
    rowptr_k<<<NBLK, 256>>>();
    csr_fill_k<<<nb_edges, TB>>>(ei);

    // ---- layer 1 ----
    gemm_tc_k<<<nb_gemm, TB>>>(x, W1, 0);
    aggregate_k<<<nb_agg, TB>>>(b1, nullptr);
    bn_stats_k<<<NSTAT, 128>>>();
    bn_final_k<<<1, 128>>>(g1, be1);

    // ---- layer 2 (BN1+ReLU fused into GEMM A-stage) ----
    gemm_tc_k<<<nb_gemm, TB>>>(nullptr, W2, 1);
    aggregate_k<<<nb_agg, TB>>>(b2, nullptr);
    bn_stats_k<<<NSTAT, 128>>>();
    bn_final_k<<<1, 128>>>(g2, be2);

    // ---- layer 3 (BN2+ReLU fused into GEMM A-stage) ----
    gemm_tc_k<<<nb_gemm, TB>>>(nullptr, W3, 1);
    aggregate_k<<<nb_agg, TB>>>(b3, out);
}